// round 2
// baseline (speedup 1.0000x reference)
#include <cuda_runtime.h>

#define BB 32
#define SS 2048
#define NROWS (BB * SS)

// Scratch: __device__ globals (no allocation allowed in kernel_launch).
__device__ float4 g_Q[NROWS];
__device__ float4 g_K[NROWS];
__device__ float4 g_V[NROWS];
__device__ float4 g_ctx[NROWS];

// ---------------------------------------------------------------------------
// 16-dim statevector circuit: qubit q lives at bit (3-q). All loops fully
// unrolled with compile-time masks so CNOTs are free register renames.
// ---------------------------------------------------------------------------

template <int Q>
__device__ __forceinline__ void rx_gate(float sr[16], float si[16], float c, float sn) {
    const int m = 1 << (3 - Q);
#pragma unroll
    for (int i = 0; i < 16; i++) {
        if (!(i & m)) {
            const int j = i | m;
            float a0r = sr[i], a0i = si[i];
            float a1r = sr[j], a1i = si[j];
            // new_a0 = c*a0 - i*sn*a1 ; new_a1 = c*a1 - i*sn*a0
            sr[i] = c * a0r + sn * a1i;
            si[i] = c * a0i - sn * a1r;
            sr[j] = c * a1r + sn * a0i;
            si[j] = c * a1i - sn * a0r;
        }
    }
}

template <int Q>
__device__ __forceinline__ void cnot_gate(float sr[16], float si[16]) {
    const int cm = 1 << (3 - Q);
    const int tm = 1 << (3 - ((Q + 1) & 3));
#pragma unroll
    for (int i = 0; i < 16; i++) {
        if ((i & cm) && !(i & tm)) {
            const int j = i | tm;
            float t;
            t = sr[i]; sr[i] = sr[j]; sr[j] = t;
            t = si[i]; si[i] = si[j]; si[j] = t;
        }
    }
}

// Apply one weight layer (4 RX + CNOT ring) to a copy of the embedded state,
// then measure <Z_q> for q=0..3.
__device__ __forceinline__ float4 layer_and_measure(
    const float er[16], const float ei[16],
    const float wc[4], const float ws[4])
{
    float sr[16], si[16];
#pragma unroll
    for (int i = 0; i < 16; i++) { sr[i] = er[i]; si[i] = ei[i]; }

    rx_gate<0>(sr, si, wc[0], ws[0]);
    rx_gate<1>(sr, si, wc[1], ws[1]);
    rx_gate<2>(sr, si, wc[2], ws[2]);
    rx_gate<3>(sr, si, wc[3], ws[3]);
    cnot_gate<0>(sr, si);
    cnot_gate<1>(sr, si);
    cnot_gate<2>(sr, si);
    cnot_gate<3>(sr, si);

    float e0 = 0.f, e1 = 0.f, e2 = 0.f, e3 = 0.f;
#pragma unroll
    for (int i = 0; i < 16; i++) {
        float p = sr[i] * sr[i] + si[i] * si[i];
        e0 += (i & 8) ? -p : p;
        e1 += (i & 4) ? -p : p;
        e2 += (i & 2) ? -p : p;
        e3 += (i & 1) ? -p : p;
    }
    return make_float4(e0, e1, e2, e3);
}

// Build the embedded state from per-row angles (RX on each wire, |0..0> init).
__device__ __forceinline__ void embed(float4 ang, float er[16], float ei[16]) {
#pragma unroll
    for (int i = 0; i < 16; i++) { er[i] = 0.f; ei[i] = 0.f; }
    er[0] = 1.f;
    float c, sn;
    sincosf(ang.x * 0.5f, &sn, &c); rx_gate<0>(er, ei, c, sn);
    sincosf(ang.y * 0.5f, &sn, &c); rx_gate<1>(er, ei, c, sn);
    sincosf(ang.z * 0.5f, &sn, &c); rx_gate<2>(er, ei, c, sn);
    sincosf(ang.w * 0.5f, &sn, &c); rx_gate<3>(er, ei, c, sn);
}

__device__ __forceinline__ void load_w(const float* __restrict__ w, float wc[4], float ws[4]) {
#pragma unroll
    for (int i = 0; i < 4; i++) sincosf(w[i] * 0.5f, &ws[i], &wc[i]);
}

// ---------------------------------------------------------------------------
// Kernel 1: x -> Q, K, V (embedding shared across the three weight layers).
// ---------------------------------------------------------------------------
__global__ void qkv_kernel(const float4* __restrict__ x,
                           const float* __restrict__ wQ,
                           const float* __restrict__ wK,
                           const float* __restrict__ wV)
{
    int idx = blockIdx.x * blockDim.x + threadIdx.x;
    if (idx >= NROWS) return;

    float er[16], ei[16];
    embed(x[idx], er, ei);

    float wc[4], ws[4];
    load_w(wQ, wc, ws); g_Q[idx] = layer_and_measure(er, ei, wc, ws);
    load_w(wK, wc, ws); g_K[idx] = layer_and_measure(er, ei, wc, ws);
    load_w(wV, wc, ws); g_V[idx] = layer_and_measure(er, ei, wc, ws);
}

// ---------------------------------------------------------------------------
// Kernel 2: flash-style attention, E=4. One thread per query; K/V chunks in
// SMEM (broadcast reads). Scores bounded in [-2,2] so no max subtraction:
// softmax = exp2(s*scale*log2e)/sum. scale*log2e folded into q.
// ---------------------------------------------------------------------------
#define ATTN_CHUNK 1024
#define ATTN_TPB   128

__device__ __forceinline__ float fast_exp2(float x) {
    float y;
    asm("ex2.approx.ftz.f32 %0, %1;" : "=f"(y) : "f"(x));
    return y;
}

__global__ void __launch_bounds__(ATTN_TPB)
attn_kernel()
{
    __shared__ float4 sK[ATTN_CHUNK];
    __shared__ float4 sV[ATTN_CHUNK];

    const int b  = blockIdx.y;
    const int qi = blockIdx.x * ATTN_TPB + threadIdx.x;

    float4 qv = g_Q[b * SS + qi];
    const float scale = 0.5f * 1.4426950408889634f;  // 1/sqrt(E) * log2(e)
    qv.x *= scale; qv.y *= scale; qv.z *= scale; qv.w *= scale;

    float den = 0.f;
    float ax = 0.f, ay = 0.f, az = 0.f, aw = 0.f;

    for (int k0 = 0; k0 < SS; k0 += ATTN_CHUNK) {
        __syncthreads();
#pragma unroll
        for (int i = threadIdx.x; i < ATTN_CHUNK; i += ATTN_TPB) {
            sK[i] = g_K[b * SS + k0 + i];
            sV[i] = g_V[b * SS + k0 + i];
        }
        __syncthreads();

#pragma unroll 8
        for (int k = 0; k < ATTN_CHUNK; k++) {
            float4 kv = sK[k];
            float s = qv.x * kv.x + qv.y * kv.y + qv.z * kv.z + qv.w * kv.w;
            float e = fast_exp2(s);
            den += e;
            float4 vv = sV[k];
            ax += e * vv.x;
            ay += e * vv.y;
            az += e * vv.z;
            aw += e * vv.w;
        }
    }

    float inv = __fdividef(1.f, den);
    g_ctx[b * SS + qi] = make_float4(ax * inv, ay * inv, az * inv, aw * inv);
}

// ---------------------------------------------------------------------------
// Kernel 3: ctx -> circuit(weights_C) -> out
// ---------------------------------------------------------------------------
__global__ void out_kernel(const float* __restrict__ wC, float4* __restrict__ out)
{
    int idx = blockIdx.x * blockDim.x + threadIdx.x;
    if (idx >= NROWS) return;

    float er[16], ei[16];
    embed(g_ctx[idx], er, ei);

    float wc[4], ws[4];
    load_w(wC, wc, ws);
    out[idx] = layer_and_measure(er, ei, wc, ws);
}

// ---------------------------------------------------------------------------

extern "C" void kernel_launch(void* const* d_in, const int* in_sizes, int n_in,
                              void* d_out, int out_size)
{
    const float4* x  = (const float4*)d_in[0];
    const float*  wQ = (const float*)d_in[1];
    const float*  wK = (const float*)d_in[2];
    const float*  wV = (const float*)d_in[3];
    const float*  wC = (const float*)d_in[4];

    qkv_kernel<<<NROWS / 128, 128>>>(x, wQ, wK, wV);

    dim3 grid(SS / ATTN_TPB, BB);
    attn_kernel<<<grid, ATTN_TPB>>>();

    out_kernel<<<NROWS / 128, 128>>>(wC, (float4*)d_out);
}

// round 3
// speedup vs baseline: 1.4871x; 1.4871x over previous
#include <cuda_runtime.h>

#define BB 32
#define SS 2048
#define NROWS (BB * SS)

// Scratch: __device__ globals (no allocation allowed in kernel_launch).
__device__ float4 g_Q[NROWS];
// Pair-packed layouts: for key pair p (rows 2p, 2p+1):
//   g_Kp[2p]   = (k0.x, k1.x, k0.y, k1.y)
//   g_Kp[2p+1] = (k0.z, k1.z, k0.w, k1.w)
__device__ float4 g_Kp[NROWS];
__device__ float4 g_Vp[NROWS];

typedef unsigned long long ull;

// ---------------------------------------------------------------------------
// Packed f32x2 helpers (sm_103a FFMA2 path — ptxas won't auto-fuse from C++)
// ---------------------------------------------------------------------------
__device__ __forceinline__ ull pack2(float lo, float hi) {
    ull r; asm("mov.b64 %0, {%1, %2};" : "=l"(r) : "f"(lo), "f"(hi)); return r;
}
__device__ __forceinline__ void unpack2(ull v, float& lo, float& hi) {
    asm("mov.b64 {%0, %1}, %2;" : "=f"(lo), "=f"(hi) : "l"(v));
}
__device__ __forceinline__ ull fma2(ull a, ull b, ull c) {
    ull d; asm("fma.rn.f32x2 %0, %1, %2, %3;" : "=l"(d) : "l"(a), "l"(b), "l"(c)); return d;
}
__device__ __forceinline__ ull mul2(ull a, ull b) {
    ull d; asm("mul.rn.f32x2 %0, %1, %2;" : "=l"(d) : "l"(a), "l"(b)); return d;
}
__device__ __forceinline__ ull add2(ull a, ull b) {
    ull d; asm("add.rn.f32x2 %0, %1, %2;" : "=l"(d) : "l"(a), "l"(b)); return d;
}
__device__ __forceinline__ float fast_exp2(float x) {
    float y; asm("ex2.approx.ftz.f32 %0, %1;" : "=f"(y) : "f"(x)); return y;
}

// ---------------------------------------------------------------------------
// 16-dim statevector circuit: qubit q lives at bit (3-q). Fully unrolled;
// CNOTs are free register renames.
// ---------------------------------------------------------------------------
template <int Q>
__device__ __forceinline__ void rx_gate(float sr[16], float si[16], float c, float sn) {
    const int m = 1 << (3 - Q);
#pragma unroll
    for (int i = 0; i < 16; i++) {
        if (!(i & m)) {
            const int j = i | m;
            float a0r = sr[i], a0i = si[i];
            float a1r = sr[j], a1i = si[j];
            sr[i] = c * a0r + sn * a1i;
            si[i] = c * a0i - sn * a1r;
            sr[j] = c * a1r + sn * a0i;
            si[j] = c * a1i - sn * a0r;
        }
    }
}

template <int Q>
__device__ __forceinline__ void cnot_gate(float sr[16], float si[16]) {
    const int cm = 1 << (3 - Q);
    const int tm = 1 << (3 - ((Q + 1) & 3));
#pragma unroll
    for (int i = 0; i < 16; i++) {
        if ((i & cm) && !(i & tm)) {
            const int j = i | tm;
            float t;
            t = sr[i]; sr[i] = sr[j]; sr[j] = t;
            t = si[i]; si[i] = si[j]; si[j] = t;
        }
    }
}

__device__ __forceinline__ float4 layer_and_measure(
    const float er[16], const float ei[16],
    const float wc[4], const float ws[4])
{
    float sr[16], si[16];
#pragma unroll
    for (int i = 0; i < 16; i++) { sr[i] = er[i]; si[i] = ei[i]; }

    rx_gate<0>(sr, si, wc[0], ws[0]);
    rx_gate<1>(sr, si, wc[1], ws[1]);
    rx_gate<2>(sr, si, wc[2], ws[2]);
    rx_gate<3>(sr, si, wc[3], ws[3]);
    cnot_gate<0>(sr, si);
    cnot_gate<1>(sr, si);
    cnot_gate<2>(sr, si);
    cnot_gate<3>(sr, si);

    float e0 = 0.f, e1 = 0.f, e2 = 0.f, e3 = 0.f;
#pragma unroll
    for (int i = 0; i < 16; i++) {
        float p = sr[i] * sr[i] + si[i] * si[i];
        e0 += (i & 8) ? -p : p;
        e1 += (i & 4) ? -p : p;
        e2 += (i & 2) ? -p : p;
        e3 += (i & 1) ? -p : p;
    }
    return make_float4(e0, e1, e2, e3);
}

__device__ __forceinline__ void embed(float4 ang, float er[16], float ei[16]) {
#pragma unroll
    for (int i = 0; i < 16; i++) { er[i] = 0.f; ei[i] = 0.f; }
    er[0] = 1.f;
    float c, sn;
    sincosf(ang.x * 0.5f, &sn, &c); rx_gate<0>(er, ei, c, sn);
    sincosf(ang.y * 0.5f, &sn, &c); rx_gate<1>(er, ei, c, sn);
    sincosf(ang.z * 0.5f, &sn, &c); rx_gate<2>(er, ei, c, sn);
    sincosf(ang.w * 0.5f, &sn, &c); rx_gate<3>(er, ei, c, sn);
}

__device__ __forceinline__ void load_w(const float* __restrict__ w, float wc[4], float ws[4]) {
#pragma unroll
    for (int i = 0; i < 4; i++) sincosf(w[i] * 0.5f, &ws[i], &wc[i]);
}

// ---------------------------------------------------------------------------
// Kernel 1: x -> Q (row layout), K, V (pair-packed layout).
// ---------------------------------------------------------------------------
__global__ void qkv_kernel(const float4* __restrict__ x,
                           const float* __restrict__ wQ,
                           const float* __restrict__ wK,
                           const float* __restrict__ wV)
{
    int idx = blockIdx.x * blockDim.x + threadIdx.x;
    if (idx >= NROWS) return;

    float er[16], ei[16];
    embed(x[idx], er, ei);

    float wc[4], ws[4];
    load_w(wQ, wc, ws); g_Q[idx] = layer_and_measure(er, ei, wc, ws);

    const int p = idx >> 1;
    const int h = idx & 1;
    float* gk = (float*)g_Kp;
    float* gv = (float*)g_Vp;

    load_w(wK, wc, ws);
    {
        float4 k = layer_and_measure(er, ei, wc, ws);
        gk[p * 8 + 0 + h] = k.x;
        gk[p * 8 + 2 + h] = k.y;
        gk[p * 8 + 4 + h] = k.z;
        gk[p * 8 + 6 + h] = k.w;
    }
    load_w(wV, wc, ws);
    {
        float4 v = layer_and_measure(er, ei, wc, ws);
        gv[p * 8 + 0 + h] = v.x;
        gv[p * 8 + 2 + h] = v.y;
        gv[p * 8 + 4 + h] = v.z;
        gv[p * 8 + 6 + h] = v.w;
    }
}

// ---------------------------------------------------------------------------
// Kernel 2: fused attention + output circuit.
// 2 queries/thread, 2 keys per packed f32x2 lane-pair. Scores in [-2,2] so
// no max subtraction: softmax = exp2(s*scale*log2e)/sum, scale folded into q.
// Epilogue runs circuit(weights_C) on ctx and writes the final output.
// ---------------------------------------------------------------------------
#define ATTN_TPB  64
#define QPT       2
#define ATTN_CHUNK 1024

__global__ void __launch_bounds__(ATTN_TPB)
attn_out_kernel(const float* __restrict__ wC, float4* __restrict__ out)
{
    __shared__ float4 sK[ATTN_CHUNK];   // pair-packed, same layout as g_Kp
    __shared__ float4 sV[ATTN_CHUNK];

    const int b     = blockIdx.y;
    const int qbase = blockIdx.x * (ATTN_TPB * QPT);
    const int t     = threadIdx.x;

    const float scale = 0.5f * 1.4426950408889634f;  // 1/sqrt(E) * log2(e)

    float4 qa = g_Q[b * SS + qbase + t];
    float4 qb = g_Q[b * SS + qbase + t + ATTN_TPB];

    const ull qa_x = pack2(qa.x * scale, qa.x * scale);
    const ull qa_y = pack2(qa.y * scale, qa.y * scale);
    const ull qa_z = pack2(qa.z * scale, qa.z * scale);
    const ull qa_w = pack2(qa.w * scale, qa.w * scale);
    const ull qb_x = pack2(qb.x * scale, qb.x * scale);
    const ull qb_y = pack2(qb.y * scale, qb.y * scale);
    const ull qb_z = pack2(qb.z * scale, qb.z * scale);
    const ull qb_w = pack2(qb.w * scale, qb.w * scale);

    ull den_a = 0, den_b = 0;
    ull aa0 = 0, aa1 = 0, aa2 = 0, aa3 = 0;
    ull ab0 = 0, ab1 = 0, ab2 = 0, ab3 = 0;

    for (int k0 = 0; k0 < SS; k0 += ATTN_CHUNK) {
        __syncthreads();
#pragma unroll
        for (int i = t; i < ATTN_CHUNK; i += ATTN_TPB) {
            sK[i] = g_Kp[b * SS + k0 + i];
            sV[i] = g_Vp[b * SS + k0 + i];
        }
        __syncthreads();

        const ulonglong2* kk = (const ulonglong2*)sK;
        const ulonglong2* vv = (const ulonglong2*)sV;

#pragma unroll 4
        for (int p = 0; p < ATTN_CHUNK / 2; p++) {
            ulonglong2 ka = kk[2 * p];      // (kx pair, ky pair)
            ulonglong2 kb = kk[2 * p + 1];  // (kz pair, kw pair)

            ull sa = fma2(qa_x, ka.x, fma2(qa_y, ka.y, fma2(qa_z, kb.x, mul2(qa_w, kb.y))));
            ull sb = fma2(qb_x, ka.x, fma2(qb_y, ka.y, fma2(qb_z, kb.x, mul2(qb_w, kb.y))));

            float s0, s1;
            unpack2(sa, s0, s1);
            ull ea = pack2(fast_exp2(s0), fast_exp2(s1));
            unpack2(sb, s0, s1);
            ull eb = pack2(fast_exp2(s0), fast_exp2(s1));

            den_a = add2(den_a, ea);
            den_b = add2(den_b, eb);

            ulonglong2 va = vv[2 * p];
            ulonglong2 vb = vv[2 * p + 1];

            aa0 = fma2(ea, va.x, aa0);
            aa1 = fma2(ea, va.y, aa1);
            aa2 = fma2(ea, vb.x, aa2);
            aa3 = fma2(ea, vb.y, aa3);
            ab0 = fma2(eb, va.x, ab0);
            ab1 = fma2(eb, va.y, ab1);
            ab2 = fma2(eb, vb.x, ab2);
            ab3 = fma2(eb, vb.y, ab3);
        }
    }

    float wc[4], ws[4];
    load_w(wC, wc, ws);

    // ---- query A ----
    {
        float d0, d1, u0, u1;
        unpack2(den_a, d0, d1);
        float inv = __fdividef(1.f, d0 + d1);
        float4 ctx;
        unpack2(aa0, u0, u1); ctx.x = (u0 + u1) * inv;
        unpack2(aa1, u0, u1); ctx.y = (u0 + u1) * inv;
        unpack2(aa2, u0, u1); ctx.z = (u0 + u1) * inv;
        unpack2(aa3, u0, u1); ctx.w = (u0 + u1) * inv;

        float er[16], ei[16];
        embed(ctx, er, ei);
        out[b * SS + qbase + t] = layer_and_measure(er, ei, wc, ws);
    }
    // ---- query B ----
    {
        float d0, d1, u0, u1;
        unpack2(den_b, d0, d1);
        float inv = __fdividef(1.f, d0 + d1);
        float4 ctx;
        unpack2(ab0, u0, u1); ctx.x = (u0 + u1) * inv;
        unpack2(ab1, u0, u1); ctx.y = (u0 + u1) * inv;
        unpack2(ab2, u0, u1); ctx.z = (u0 + u1) * inv;
        unpack2(ab3, u0, u1); ctx.w = (u0 + u1) * inv;

        float er[16], ei[16];
        embed(ctx, er, ei);
        out[b * SS + qbase + t + ATTN_TPB] = layer_and_measure(er, ei, wc, ws);
    }
}

// ---------------------------------------------------------------------------

extern "C" void kernel_launch(void* const* d_in, const int* in_sizes, int n_in,
                              void* d_out, int out_size)
{
    const float4* x  = (const float4*)d_in[0];
    const float*  wQ = (const float*)d_in[1];
    const float*  wK = (const float*)d_in[2];
    const float*  wV = (const float*)d_in[3];
    const float*  wC = (const float*)d_in[4];

    qkv_kernel<<<NROWS / 128, 128>>>(x, wQ, wK, wV);

    dim3 grid(SS / (ATTN_TPB * QPT), BB);
    attn_out_kernel<<<grid, ATTN_TPB>>>(wC, (float4*)d_out);
}